// round 14
// baseline (speedup 1.0000x reference)
#include <cuda_runtime.h>
#include <math.h>

#define BB 64
#define SS 512
#define HID 40
#define HEADS 4
#define DH 10
#define INTER 20
#define TT (BB*SS)
#define NBH (BB*HEADS)     // 256
#define KHALF (SS/2)       // 256

typedef unsigned long long u64;

// scratch (allocation-free rule: __device__ globals)
// q,k,v layout [bh][s][dh]; pacc [kh][bh][s][dh]
__device__ __align__(16) float g_q[NBH*SS*DH];
__device__ __align__(16) float g_k[NBH*SS*DH];
__device__ __align__(16) float g_v[NBH*SS*DH];
__device__ __align__(16) float g_pacc[2*NBH*SS*DH];
__device__ __align__(16) float g_pl[2*NBH*SS];

__device__ __forceinline__ float ex2(float x){
    float y; asm("ex2.approx.f32 %0, %1;" : "=f"(y) : "f"(x)); return y;
}
__device__ __forceinline__ u64 pk2(float x, float y){
    u64 r; asm("mov.b64 %0, {%1, %2};" : "=l"(r) : "f"(x), "f"(y)); return r;
}
__device__ __forceinline__ float2 upk2(u64 a){
    float2 r; asm("mov.b64 {%0, %1}, %2;" : "=f"(r.x), "=f"(r.y) : "l"(a)); return r;
}
__device__ __forceinline__ u64 fma2(u64 a, u64 b, u64 c){
    u64 d; asm("fma.rn.f32x2 %0, %1, %2, %3;" : "=l"(d) : "l"(a), "l"(b), "l"(c)); return d;
}

// ---------------- Kernel 1: LN1 + QKV, register-tiled 4 tokens x 8 outputs (R12) ----------------
__global__ void __launch_bounds__(240) k_ln_qkv(
    const float* __restrict__ x,
    const float* __restrict__ g1, const float* __restrict__ b1,
    const float* __restrict__ Wq, const float* __restrict__ bq,
    const float* __restrict__ Wk, const float* __restrict__ bk,
    const float* __restrict__ Wv, const float* __restrict__ bv)
{
    __shared__ __align__(16) float Ws[HID*120];   // [i][o]: 0-39 q, 40-79 k, 80-119 v
    __shared__ __align__(16) float bs[120];
    __shared__ __align__(16) u64  hd[HID*64];     // duplicated (h,h), [i][tok]
    __shared__ __align__(16) float qkv_s[64*120]; // bounce buffer [tok][o]
    __shared__ float g1s[HID], b1s_[HID];

    const int tid = threadIdx.x;
    const int b   = blockIdx.x >> 3;
    const int s0  = (blockIdx.x & 7) << 6;
    const int t0  = blockIdx.x * 64;

    // stage weights (vectorized, coalesced)
    for (int idx = tid; idx < 400; idx += 240) {
        int i = idx / 10, c = idx % 10;
        *(float4*)&Ws[i*120 +      c*4] = *(const float4*)&Wq[i*40 + c*4];
        *(float4*)&Ws[i*120 + 40 + c*4] = *(const float4*)&Wk[i*40 + c*4];
        *(float4*)&Ws[i*120 + 80 + c*4] = *(const float4*)&Wv[i*40 + c*4];
    }
    if (tid < HID) {
        bs[tid] = bq[tid]; bs[40+tid] = bk[tid]; bs[80+tid] = bv[tid];
        g1s[tid] = g1[tid]; b1s_[tid] = b1[tid];
    }
    __syncthreads();

    // LN: threads 0-63, one token each, direct GMEM reads
    if (tid < 64) {
        const float4* xr = (const float4*)(x + (size_t)(t0 + tid)*HID);
        float xv[HID]; float s1 = 0.f, s2 = 0.f;
#pragma unroll
        for (int i4 = 0; i4 < 10; i4++) {
            float4 v = xr[i4];
            xv[4*i4]=v.x; xv[4*i4+1]=v.y; xv[4*i4+2]=v.z; xv[4*i4+3]=v.w;
            s1 += v.x + v.y + v.z + v.w;
            s2 += v.x*v.x + v.y*v.y + v.z*v.z + v.w*v.w;
        }
        float mu = s1 * (1.f/HID);
        float var = s2 * (1.f/HID) - mu*mu;
        float rs = rsqrtf(var + 1e-5f);
#pragma unroll
        for (int i = 0; i < HID; i++) {
            float hv = (xv[i] - mu)*rs*g1s[i] + b1s_[i];
            hd[i*64 + tid] = pk2(hv, hv);
        }
    }
    __syncthreads();

    // main GEMM: 4 tokens x 8 outputs per thread
    const int tg = tid & 15;
    const int og = tid / 16;          // 0..14
    const int tok0 = tg * 4;
    const int o0 = og * 8;

    u64 acc[4][4];
    {
        ulonglong2 b01 = *(const ulonglong2*)&bs[o0];
        ulonglong2 b23 = *(const ulonglong2*)&bs[o0+4];
        u64 bp[4] = {b01.x, b01.y, b23.x, b23.y};
#pragma unroll
        for (int j = 0; j < 4; j++)
#pragma unroll
            for (int p = 0; p < 4; p++) acc[j][p] = bp[p];
    }

#pragma unroll
    for (int i = 0; i < HID; i++) {
        ulonglong2 h01 = *(const ulonglong2*)&hd[i*64 + tok0];
        ulonglong2 h23 = *(const ulonglong2*)&hd[i*64 + tok0 + 2];
        ulonglong2 w01 = *(const ulonglong2*)&Ws[i*120 + o0];       // uniform -> broadcast
        ulonglong2 w23 = *(const ulonglong2*)&Ws[i*120 + o0 + 4];
        u64 hh[4] = {h01.x, h01.y, h23.x, h23.y};
        u64 ww[4] = {w01.x, w01.y, w23.x, w23.y};
#pragma unroll
        for (int j = 0; j < 4; j++) {
#pragma unroll
            for (int p = 0; p < 4; p++)
                acc[j][p] = fma2(hh[j], ww[p], acc[j][p]);
        }
    }

    // bounce to smem
#pragma unroll
    for (int j = 0; j < 4; j++)
#pragma unroll
        for (int p = 0; p < 4; p++)
            *(float2*)&qkv_s[(tok0 + j)*120 + o0 + 2*p] = upk2(acc[j][p]);
    __syncthreads();

    // coalesced stores: 12 segments (which,head) of 640 contiguous floats each
    for (int idx = tid; idx < 1920; idx += 240) {
        int seg = idx / 160, r = idx % 160;
        int which = seg >> 2, hh = seg & 3;
        int base = which*40 + hh*10;
        int l = r * 4;
        float4 v;
        v.x = qkv_s[(l/10)*120 + base + (l%10)]; l++;
        v.y = qkv_s[(l/10)*120 + base + (l%10)]; l++;
        v.z = qkv_s[(l/10)*120 + base + (l%10)]; l++;
        v.w = qkv_s[(l/10)*120 + base + (l%10)];
        float* dst = (which == 0) ? g_q : (which == 1) ? g_k : g_v;
        *(float4*)&dst[(((size_t)b*HEADS + hh)*SS + s0)*DH + r*4] = v;
    }
}

// ---------------- Kernel 2: attention, split-K, 4 queries/thread (R13) ----------------
__global__ void __launch_bounds__(128) k_attn()
{
    __shared__ __align__(16) float ks[KHALF*DH];
    __shared__ __align__(16) float vs[KHALF*DH];

    const int tid = threadIdx.x;
    const int blk = blockIdx.x;
    const int kh  = blk & 1;
    const int bh  = blk >> 1;

    const float4* kb = (const float4*)(g_k + (size_t)bh*SS*DH + kh*KHALF*DH);
    const float4* vb = (const float4*)(g_v + (size_t)bh*SS*DH + kh*KHALF*DH);
#pragma unroll
    for (int i = 0; i < KHALF*DH/4/128; i++) {
        ((float4*)ks)[tid + i*128] = kb[tid + i*128];
        ((float4*)vs)[tid + i*128] = vb[tid + i*128];
    }

    const float scale = 0.316227766016838f * 1.44269504088896f; // 1/sqrt(DH)*log2e
    u64 q[4][5];
#pragma unroll
    for (int g = 0; g < 4; g++) {
        const float* p = g_q + ((size_t)bh*SS + g*128 + tid)*DH;
#pragma unroll
        for (int j = 0; j < 5; j++)
            q[g][j] = pk2(p[2*j]*scale, p[2*j+1]*scale);
    }
    __syncthreads();

    float l[4] = {0.f, 0.f, 0.f, 0.f};
    u64 a[4][5];
#pragma unroll
    for (int g = 0; g < 4; g++)
#pragma unroll
        for (int j = 0; j < 5; j++) a[g][j] = 0ULL;

#pragma unroll 2
    for (int s = 0; s < KHALF; s++) {
        const u64* kk = (const u64*)&ks[s*DH];
        u64 k0=kk[0], k1=kk[1], k2=kk[2], k3=kk[3], k4=kk[4];
        u64 d0 = 0ULL, d1 = 0ULL, d2 = 0ULL, d3 = 0ULL;
        d0 = fma2(q[0][0],k0,d0); d1 = fma2(q[1][0],k0,d1); d2 = fma2(q[2][0],k0,d2); d3 = fma2(q[3][0],k0,d3);
        d0 = fma2(q[0][1],k1,d0); d1 = fma2(q[1][1],k1,d1); d2 = fma2(q[2][1],k1,d2); d3 = fma2(q[3][1],k1,d3);
        d0 = fma2(q[0][2],k2,d0); d1 = fma2(q[1][2],k2,d1); d2 = fma2(q[2][2],k2,d2); d3 = fma2(q[3][2],k2,d3);
        d0 = fma2(q[0][3],k3,d0); d1 = fma2(q[1][3],k3,d1); d2 = fma2(q[2][3],k3,d2); d3 = fma2(q[3][3],k3,d3);
        d0 = fma2(q[0][4],k4,d0); d1 = fma2(q[1][4],k4,d1); d2 = fma2(q[2][4],k4,d2); d3 = fma2(q[3][4],k4,d3);

        float2 f0 = upk2(d0), f1 = upk2(d1), f2 = upk2(d2), f3 = upk2(d3);
        float p0 = ex2(f0.x + f0.y);   // scores tiny: no max subtraction needed
        float p1 = ex2(f1.x + f1.y);
        float p2 = ex2(f2.x + f2.y);
        float p3 = ex2(f3.x + f3.y);
        l[0] += p0; l[1] += p1; l[2] += p2; l[3] += p3;

        const u64* vv = (const u64*)&vs[s*DH];
        u64 v0=vv[0], v1=vv[1], v2=vv[2], v3=vv[3], v4=vv[4];
        u64 pp0 = pk2(p0,p0), pp1 = pk2(p1,p1), pp2 = pk2(p2,p2), pp3 = pk2(p3,p3);
        a[0][0]=fma2(pp0,v0,a[0][0]); a[1][0]=fma2(pp1,v0,a[1][0]); a[2][0]=fma2(pp2,v0,a[2][0]); a[3][0]=fma2(pp3,v0,a[3][0]);
        a[0][1]=fma2(pp0,v1,a[0][1]); a[1][1]=fma2(pp1,v1,a[1][1]); a[2][1]=fma2(pp2,v1,a[2][1]); a[3][1]=fma2(pp3,v1,a[3][1]);
        a[0][2]=fma2(pp0,v2,a[0][2]); a[1][2]=fma2(pp1,v2,a[1][2]); a[2][2]=fma2(pp2,v2,a[2][2]); a[3][2]=fma2(pp3,v2,a[3][2]);
        a[0][3]=fma2(pp0,v3,a[0][3]); a[1][3]=fma2(pp1,v3,a[1][3]); a[2][3]=fma2(pp2,v3,a[2][3]); a[3][3]=fma2(pp3,v3,a[3][3]);
        a[0][4]=fma2(pp0,v4,a[0][4]); a[1][4]=fma2(pp1,v4,a[1][4]); a[2][4]=fma2(pp2,v4,a[2][4]); a[3][4]=fma2(pp3,v4,a[3][4]);
    }

#pragma unroll
    for (int g = 0; g < 4; g++) {
        int qi = g*128 + tid;
        float* pacc = g_pacc + (((size_t)kh*NBH + bh)*SS + qi)*DH;
#pragma unroll
        for (int j = 0; j < 5; j++)
            *(float2*)&pacc[2*j] = upk2(a[g][j]);
        g_pl[((size_t)kh*NBH + bh)*SS + qi] = l[g];
    }
}

// ---------------- Kernel 3: combine + Wo + residual + LN2 + FFN + residual ----------------
// block 128 = 4 warps; lane = token (32 tokens); warp w = output slice / head (warp-uniform weights).
__global__ void __launch_bounds__(128) k_out_ffn(
    const float* __restrict__ x,
    const float* __restrict__ Wo, const float* __restrict__ bo,
    const float* __restrict__ g2, const float* __restrict__ b2g,
    const float* __restrict__ W1, const float* __restrict__ b1f,
    const float* __restrict__ W2, const float* __restrict__ b2f,
    float* __restrict__ out)
{
    __shared__ __align__(16) float Wos[HID*HID];
    __shared__ __align__(16) float W1s[HID*INTER];
    __shared__ __align__(16) float W2s[INTER*HID];
    __shared__ __align__(16) u64  cs[32*41];     // packed (ctx,ctx), stride 41
    __shared__ __align__(16) float ao_s[32*41];  // stride 41: conflict-free lane reads
    __shared__ __align__(16) u64  h2s[32*41];    // packed (h2,h2)
    __shared__ __align__(16) float h2f[32*41];   // scalar copy for W1 GEMM
    __shared__ __align__(16) float it_s[32*21];  // stride 21
    __shared__ float bos[HID], b1s[INTER], b2s[HID], g2s[HID], b2gs[HID];

    const int tid  = threadIdx.x;
    const int w    = tid >> 5;
    const int lane = tid & 31;

    for (int i = tid; i < HID*HID; i += 128)   Wos[i] = Wo[i];
    for (int i = tid; i < HID*INTER; i += 128) W1s[i] = W1[i];
    for (int i = tid; i < INTER*HID; i += 128) W2s[i] = W2[i];
    if (tid < HID)   { bos[tid] = bo[tid]; b2s[tid] = b2f[tid]; g2s[tid] = g2[tid]; b2gs[tid] = b2g[tid]; }
    if (tid < INTER) { b1s[tid] = b1f[tid]; }

    const int tok = lane;
    const int t = blockIdx.x*32 + lane;
    const int b = t / SS, s = t % SS;
    const int base = w * 10;

    // combine split-K partials: warp w handles head w for its lane's token
    {
        const int bh = b*HEADS + w;
        float l = g_pl[(size_t)bh*SS + s] + g_pl[((size_t)NBH + bh)*SS + s];
        float inv = 1.f / l;
        const float* p0 = g_pacc + ((size_t)bh*SS + s)*DH;
        const float* p1 = g_pacc + (((size_t)NBH + bh)*SS + s)*DH;
#pragma unroll
        for (int j = 0; j < 5; j++) {
            float2 a0 = *(const float2*)&p0[2*j];
            float2 a1 = *(const float2*)&p1[2*j];
            float cx = (a0.x + a1.x) * inv;
            float cy = (a0.y + a1.y) * inv;
            cs[tok*41 + w*DH + 2*j]     = pk2(cx, cx);
            cs[tok*41 + w*DH + 2*j + 1] = pk2(cy, cy);
        }
    }
    __syncthreads();

    // ao[base..base+10) = ctx @ Wo + bo + x
    u64 acc[5];
#pragma unroll
    for (int j = 0; j < 5; j++) acc[j] = *(const u64*)&bos[base + 2*j];
#pragma unroll
    for (int i = 0; i < HID; i++) {
        u64 c2 = cs[tok*41 + i];
        const u64* wr = (const u64*)&Wos[i*HID + base];   // uniform -> broadcast
#pragma unroll
        for (int j = 0; j < 5; j++) acc[j] = fma2(c2, wr[j], acc[j]);
    }
    float aoc[10];
#pragma unroll
    for (int j = 0; j < 5; j++) {
        float2 v = upk2(acc[j]);
        float2 xv = *(const float2*)&x[(size_t)t*HID + base + 2*j];
        aoc[2*j]   = v.x + xv.x;
        aoc[2*j+1] = v.y + xv.y;
        ao_s[tok*41 + base + 2*j]   = aoc[2*j];
        ao_s[tok*41 + base + 2*j+1] = aoc[2*j+1];
    }
    __syncthreads();

    // LN2 (single pass, conflict-free scalar reads)
    float s1 = 0.f, s2 = 0.f;
#pragma unroll
    for (int i = 0; i < HID; i++) {
        float v = ao_s[tok*41 + i];
        s1 += v; s2 += v*v;
    }
    float mu = s1 * (1.f/HID);
    float var = s2 * (1.f/HID) - mu*mu;
    float rs = rsqrtf(var + 1e-5f);
#pragma unroll
    for (int i = base; i < base + 10; i++) {
        float hv = (ao_s[tok*41 + i] - mu)*rs*g2s[i] + b2gs[i];
        h2s[tok*41 + i] = pk2(hv, hv);
        h2f[tok*41 + i] = hv;
    }
    __syncthreads();

    // inter[5w..5w+5) = gelu(h2 @ W1 + b1)
    {
        const int ibase = w * 5;
        float it[5];
#pragma unroll
        for (int o = 0; o < 5; o++) it[o] = b1s[ibase + o];
#pragma unroll
        for (int i = 0; i < HID; i++) {
            float hi = h2f[tok*41 + i];
            const float* wr = &W1s[i*INTER + ibase];      // uniform -> broadcast
#pragma unroll
            for (int o = 0; o < 5; o++) it[o] = fmaf(hi, wr[o], it[o]);
        }
#pragma unroll
        for (int o = 0; o < 5; o++) {
            float z = it[o];
            it_s[tok*21 + ibase + o] = 0.5f * z * (1.f + erff(z * 0.70710678118654752f));
        }
    }
    __syncthreads();

    // out[base..base+10) = inter @ W2 + b2 + ao
    u64 acc2[5];
#pragma unroll
    for (int j = 0; j < 5; j++) acc2[j] = *(const u64*)&b2s[base + 2*j];
#pragma unroll
    for (int i = 0; i < INTER; i++) {
        float iv = it_s[tok*21 + i];
        u64 i2 = pk2(iv, iv);
        const u64* wr = (const u64*)&W2s[i*HID + base];   // uniform -> broadcast
#pragma unroll
        for (int j = 0; j < 5; j++) acc2[j] = fma2(i2, wr[j], acc2[j]);
    }
#pragma unroll
    for (int j = 0; j < 5; j++) {
        float2 v = upk2(acc2[j]);
        float2 o; o.x = v.x + aoc[2*j]; o.y = v.y + aoc[2*j+1];
        *(float2*)&out[(size_t)t*HID + base + 2*j] = o;
    }
}

extern "C" void kernel_launch(void* const* d_in, const int* in_sizes, int n_in,
                              void* d_out, int out_size)
{
    const float* x    = (const float*)d_in[0];
    const float* ln1g = (const float*)d_in[1];
    const float* ln1b = (const float*)d_in[2];
    const float* Wq   = (const float*)d_in[3];
    const float* bq   = (const float*)d_in[4];
    const float* Wk   = (const float*)d_in[5];
    const float* bk   = (const float*)d_in[6];
    const float* Wv   = (const float*)d_in[7];
    const float* bv   = (const float*)d_in[8];
    const float* Wo   = (const float*)d_in[9];
    const float* bo   = (const float*)d_in[10];
    const float* ln2g = (const float*)d_in[11];
    const float* ln2b = (const float*)d_in[12];
    const float* W1   = (const float*)d_in[13];
    const float* b1   = (const float*)d_in[14];
    const float* W2   = (const float*)d_in[15];
    const float* b2   = (const float*)d_in[16];
    float* out = (float*)d_out;

    k_ln_qkv<<<TT/64, 240>>>(x, ln1g, ln1b, Wq, bq, Wk, bk, Wv, bv);
    k_attn<<<NBH*2, 128>>>();
    k_out_ffn<<<TT/32, 128>>>(x, Wo, bo, ln2g, ln2b, W1, b1, W2, b2, out);
}

// round 15
// speedup vs baseline: 1.5512x; 1.5512x over previous
#include <cuda_runtime.h>
#include <math.h>

#define BB 64
#define SS 512
#define HID 40
#define HEADS 4
#define DH 10
#define INTER 20
#define TT (BB*SS)
#define NBH (BB*HEADS)     // 256
#define KHALF (SS/2)       // 256

typedef unsigned long long u64;

// scratch (allocation-free rule: __device__ globals)
// q,k,v layout [bh][s][dh]; pacc [kh][bh][s][dh]
__device__ __align__(16) float g_q[NBH*SS*DH];
__device__ __align__(16) float g_k[NBH*SS*DH];
__device__ __align__(16) float g_v[NBH*SS*DH];
__device__ __align__(16) float g_pacc[2*NBH*SS*DH];
__device__ __align__(16) float g_pl[2*NBH*SS];

__device__ __forceinline__ float ex2(float x){
    float y; asm("ex2.approx.f32 %0, %1;" : "=f"(y) : "f"(x)); return y;
}
__device__ __forceinline__ u64 pk2(float x, float y){
    u64 r; asm("mov.b64 %0, {%1, %2};" : "=l"(r) : "f"(x), "f"(y)); return r;
}
__device__ __forceinline__ float2 upk2(u64 a){
    float2 r; asm("mov.b64 {%0, %1}, %2;" : "=f"(r.x), "=f"(r.y) : "l"(a)); return r;
}
__device__ __forceinline__ u64 fma2(u64 a, u64 b, u64 c){
    u64 d; asm("fma.rn.f32x2 %0, %1, %2, %3;" : "=l"(d) : "l"(a), "l"(b), "l"(c)); return d;
}

// ---------------- Kernel 1: LN1 + QKV, register-tiled 4 tokens x 8 outputs ----------------
// R12 structure; hd and qkv_s aliased in one buffer to cut smem 71->51 KB (4 blocks/SM).
__global__ void __launch_bounds__(240) k_ln_qkv(
    const float* __restrict__ x,
    const float* __restrict__ g1, const float* __restrict__ b1,
    const float* __restrict__ Wq, const float* __restrict__ bq,
    const float* __restrict__ Wk, const float* __restrict__ bk,
    const float* __restrict__ Wv, const float* __restrict__ bv)
{
    __shared__ __align__(16) float Ws[HID*120];   // [i][o]: 0-39 q, 40-79 k, 80-119 v
    __shared__ __align__(16) float bs[120];
    __shared__ __align__(16) char sbuf[64*120*4]; // hd (20.5KB) then qkv_s (30.7KB)
    __shared__ float g1s[HID], b1s_[HID];

    u64*   hd    = (u64*)sbuf;      // duplicated (h,h), [i][tok], HID*64 u64
    float* qkv_s = (float*)sbuf;    // bounce buffer [tok][o], 64*120 floats

    const int tid = threadIdx.x;
    const int b   = blockIdx.x >> 3;
    const int s0  = (blockIdx.x & 7) << 6;
    const int t0  = blockIdx.x * 64;

    // stage weights (vectorized, coalesced)
    for (int idx = tid; idx < 400; idx += 240) {
        int i = idx / 10, c = idx % 10;
        *(float4*)&Ws[i*120 +      c*4] = *(const float4*)&Wq[i*40 + c*4];
        *(float4*)&Ws[i*120 + 40 + c*4] = *(const float4*)&Wk[i*40 + c*4];
        *(float4*)&Ws[i*120 + 80 + c*4] = *(const float4*)&Wv[i*40 + c*4];
    }
    if (tid < HID) {
        bs[tid] = bq[tid]; bs[40+tid] = bk[tid]; bs[80+tid] = bv[tid];
        g1s[tid] = g1[tid]; b1s_[tid] = b1[tid];
    }
    __syncthreads();

    // LN: threads 0-63, one token each, direct GMEM reads
    if (tid < 64) {
        const float4* xr = (const float4*)(x + (size_t)(t0 + tid)*HID);
        float xv[HID]; float s1 = 0.f, s2 = 0.f;
#pragma unroll
        for (int i4 = 0; i4 < 10; i4++) {
            float4 v = xr[i4];
            xv[4*i4]=v.x; xv[4*i4+1]=v.y; xv[4*i4+2]=v.z; xv[4*i4+3]=v.w;
            s1 += v.x + v.y + v.z + v.w;
            s2 += v.x*v.x + v.y*v.y + v.z*v.z + v.w*v.w;
        }
        float mu = s1 * (1.f/HID);
        float var = s2 * (1.f/HID) - mu*mu;
        float rs = rsqrtf(var + 1e-5f);
#pragma unroll
        for (int i = 0; i < HID; i++) {
            float hv = (xv[i] - mu)*rs*g1s[i] + b1s_[i];
            hd[i*64 + tid] = pk2(hv, hv);
        }
    }
    __syncthreads();

    // main GEMM: 4 tokens x 8 outputs per thread
    const int tg = tid & 15;
    const int og = tid / 16;          // 0..14
    const int tok0 = tg * 4;
    const int o0 = og * 8;

    u64 acc[4][4];
    {
        ulonglong2 b01 = *(const ulonglong2*)&bs[o0];
        ulonglong2 b23 = *(const ulonglong2*)&bs[o0+4];
        u64 bp[4] = {b01.x, b01.y, b23.x, b23.y};
#pragma unroll
        for (int j = 0; j < 4; j++)
#pragma unroll
            for (int p = 0; p < 4; p++) acc[j][p] = bp[p];
    }

#pragma unroll
    for (int i = 0; i < HID; i++) {
        ulonglong2 h01 = *(const ulonglong2*)&hd[i*64 + tok0];
        ulonglong2 h23 = *(const ulonglong2*)&hd[i*64 + tok0 + 2];
        ulonglong2 w01 = *(const ulonglong2*)&Ws[i*120 + o0];       // uniform -> broadcast
        ulonglong2 w23 = *(const ulonglong2*)&Ws[i*120 + o0 + 4];
        u64 hh[4] = {h01.x, h01.y, h23.x, h23.y};
        u64 ww[4] = {w01.x, w01.y, w23.x, w23.y};
#pragma unroll
        for (int j = 0; j < 4; j++) {
#pragma unroll
            for (int p = 0; p < 4; p++)
                acc[j][p] = fma2(hh[j], ww[p], acc[j][p]);
        }
    }
    __syncthreads();   // all hd reads done before qkv_s overwrites the buffer

    // bounce to smem (aliased buffer)
#pragma unroll
    for (int j = 0; j < 4; j++)
#pragma unroll
        for (int p = 0; p < 4; p++)
            *(float2*)&qkv_s[(tok0 + j)*120 + o0 + 2*p] = upk2(acc[j][p]);
    __syncthreads();

    // coalesced stores: 12 segments (which,head) of 640 contiguous floats each
    for (int idx = tid; idx < 1920; idx += 240) {
        int seg = idx / 160, r = idx % 160;
        int which = seg >> 2, hh = seg & 3;
        int base = which*40 + hh*10;
        int l = r * 4;
        float4 v;
        v.x = qkv_s[(l/10)*120 + base + (l%10)]; l++;
        v.y = qkv_s[(l/10)*120 + base + (l%10)]; l++;
        v.z = qkv_s[(l/10)*120 + base + (l%10)]; l++;
        v.w = qkv_s[(l/10)*120 + base + (l%10)];
        float* dst = (which == 0) ? g_q : (which == 1) ? g_k : g_v;
        *(float4*)&dst[(((size_t)b*HEADS + hh)*SS + s0)*DH + r*4] = v;
    }
}

// ---------------- Kernel 2: attention, split-K, 4 queries/thread (R12) ----------------
__global__ void __launch_bounds__(128) k_attn()
{
    __shared__ __align__(16) float ks[KHALF*DH];
    __shared__ __align__(16) float vs[KHALF*DH];

    const int tid = threadIdx.x;
    const int blk = blockIdx.x;
    const int kh  = blk & 1;
    const int bh  = blk >> 1;

    const float4* kb = (const float4*)(g_k + (size_t)bh*SS*DH + kh*KHALF*DH);
    const float4* vb = (const float4*)(g_v + (size_t)bh*SS*DH + kh*KHALF*DH);
#pragma unroll
    for (int i = 0; i < KHALF*DH/4/128; i++) {
        ((float4*)ks)[tid + i*128] = kb[tid + i*128];
        ((float4*)vs)[tid + i*128] = vb[tid + i*128];
    }

    const float scale = 0.316227766016838f * 1.44269504088896f; // 1/sqrt(DH)*log2e
    u64 q[4][5];
#pragma unroll
    for (int g = 0; g < 4; g++) {
        const float* p = g_q + ((size_t)bh*SS + g*128 + tid)*DH;
#pragma unroll
        for (int j = 0; j < 5; j++)
            q[g][j] = pk2(p[2*j]*scale, p[2*j+1]*scale);
    }
    __syncthreads();

    float l[4] = {0.f, 0.f, 0.f, 0.f};
    u64 a[4][5];
#pragma unroll
    for (int g = 0; g < 4; g++)
#pragma unroll
        for (int j = 0; j < 5; j++) a[g][j] = 0ULL;

#pragma unroll 2
    for (int s = 0; s < KHALF; s++) {
        const u64* kk = (const u64*)&ks[s*DH];
        u64 k0=kk[0], k1=kk[1], k2=kk[2], k3=kk[3], k4=kk[4];
        u64 d0 = 0ULL, d1 = 0ULL, d2 = 0ULL, d3 = 0ULL;
        d0 = fma2(q[0][0],k0,d0); d1 = fma2(q[1][0],k0,d1); d2 = fma2(q[2][0],k0,d2); d3 = fma2(q[3][0],k0,d3);
        d0 = fma2(q[0][1],k1,d0); d1 = fma2(q[1][1],k1,d1); d2 = fma2(q[2][1],k1,d2); d3 = fma2(q[3][1],k1,d3);
        d0 = fma2(q[0][2],k2,d0); d1 = fma2(q[1][2],k2,d1); d2 = fma2(q[2][2],k2,d2); d3 = fma2(q[3][2],k2,d3);
        d0 = fma2(q[0][3],k3,d0); d1 = fma2(q[1][3],k3,d1); d2 = fma2(q[2][3],k3,d2); d3 = fma2(q[3][3],k3,d3);
        d0 = fma2(q[0][4],k4,d0); d1 = fma2(q[1][4],k4,d1); d2 = fma2(q[2][4],k4,d2); d3 = fma2(q[3][4],k4,d3);

        float2 f0 = upk2(d0), f1 = upk2(d1), f2 = upk2(d2), f3 = upk2(d3);
        float p0 = ex2(f0.x + f0.y);   // scores tiny: no max subtraction needed
        float p1 = ex2(f1.x + f1.y);
        float p2 = ex2(f2.x + f2.y);
        float p3 = ex2(f3.x + f3.y);
        l[0] += p0; l[1] += p1; l[2] += p2; l[3] += p3;

        const u64* vv = (const u64*)&vs[s*DH];
        u64 v0=vv[0], v1=vv[1], v2=vv[2], v3=vv[3], v4=vv[4];
        u64 pp0 = pk2(p0,p0), pp1 = pk2(p1,p1), pp2 = pk2(p2,p2), pp3 = pk2(p3,p3);
        a[0][0]=fma2(pp0,v0,a[0][0]); a[1][0]=fma2(pp1,v0,a[1][0]); a[2][0]=fma2(pp2,v0,a[2][0]); a[3][0]=fma2(pp3,v0,a[3][0]);
        a[0][1]=fma2(pp0,v1,a[0][1]); a[1][1]=fma2(pp1,v1,a[1][1]); a[2][1]=fma2(pp2,v1,a[2][1]); a[3][1]=fma2(pp3,v1,a[3][1]);
        a[0][2]=fma2(pp0,v2,a[0][2]); a[1][2]=fma2(pp1,v2,a[1][2]); a[2][2]=fma2(pp2,v2,a[2][2]); a[3][2]=fma2(pp3,v2,a[3][2]);
        a[0][3]=fma2(pp0,v3,a[0][3]); a[1][3]=fma2(pp1,v3,a[1][3]); a[2][3]=fma2(pp2,v3,a[2][3]); a[3][3]=fma2(pp3,v3,a[3][3]);
        a[0][4]=fma2(pp0,v4,a[0][4]); a[1][4]=fma2(pp1,v4,a[1][4]); a[2][4]=fma2(pp2,v4,a[2][4]); a[3][4]=fma2(pp3,v4,a[3][4]);
    }

#pragma unroll
    for (int g = 0; g < 4; g++) {
        int qi = g*128 + tid;
        float* pacc = g_pacc + (((size_t)kh*NBH + bh)*SS + qi)*DH;
#pragma unroll
        for (int j = 0; j < 5; j++)
            *(float2*)&pacc[2*j] = upk2(a[g][j]);
        g_pl[((size_t)kh*NBH + bh)*SS + qi] = l[g];
    }
}

// ---------------- Kernel 3: combine + Wo + residual + LN2 + FFN + residual (R12/R8) ----------------
__global__ void __launch_bounds__(128) k_out_ffn(
    const float* __restrict__ x,
    const float* __restrict__ Wo, const float* __restrict__ bo,
    const float* __restrict__ g2, const float* __restrict__ b2g,
    const float* __restrict__ W1, const float* __restrict__ b1f,
    const float* __restrict__ W2, const float* __restrict__ b2f,
    float* __restrict__ out)
{
    __shared__ __align__(16) float Wos[HID*HID];
    __shared__ __align__(16) float W1s[HID*INTER];
    __shared__ __align__(16) float W2s[INTER*HID];
    __shared__ __align__(16) u64  cs[32*41];
    __shared__ __align__(16) float ao_s[32*HID];
    __shared__ __align__(16) u64  h2s[32*41];
    __shared__ __align__(16) float it_s[32*INTER];
    __shared__ float bos[HID], b1s[INTER], b2s[HID], g2s[HID], b2gs[HID];

    const int tid = threadIdx.x;
    for (int i = tid; i < HID*HID; i += 128)   Wos[i] = Wo[i];
    for (int i = tid; i < HID*INTER; i += 128) W1s[i] = W1[i];
    for (int i = tid; i < INTER*HID; i += 128) W2s[i] = W2[i];
    if (tid < HID)   { bos[tid] = bo[tid]; b2s[tid] = b2f[tid]; g2s[tid] = g2[tid]; b2gs[tid] = b2g[tid]; }
    if (tid < INTER) { b1s[tid] = b1f[tid]; }

    const int tok  = tid >> 2;
    const int part = tid & 3;
    const int t = blockIdx.x*32 + tok;
    const int b = t / SS, s = t % SS;
    const int base = part * 10;

    // combine split-K partials for head `part` of this token
    {
        const int bh = b*HEADS + part;
        const float* p0 = g_pacc + (((size_t)0*NBH + bh)*SS + s)*DH;
        const float* p1 = g_pacc + (((size_t)1*NBH + bh)*SS + s)*DH;
        float l = g_pl[((size_t)0*NBH + bh)*SS + s] + g_pl[((size_t)1*NBH + bh)*SS + s];
        float inv = 1.f / l;
#pragma unroll
        for (int j = 0; j < 5; j++) {
            float2 a0 = *(const float2*)&p0[2*j];
            float2 a1 = *(const float2*)&p1[2*j];
            float cx = (a0.x + a1.x) * inv;
            float cy = (a0.y + a1.y) * inv;
            cs[tok*41 + part*DH + 2*j]     = pk2(cx, cx);
            cs[tok*41 + part*DH + 2*j + 1] = pk2(cy, cy);
        }
    }
    __syncthreads();

    // ao[base..base+10) = ctx @ Wo + bo + x
    u64 acc[5];
#pragma unroll
    for (int j = 0; j < 5; j++) acc[j] = *(const u64*)&bos[base + 2*j];
#pragma unroll
    for (int i = 0; i < HID; i++) {
        u64 c2 = cs[tok*41 + i];
        const u64* wr = (const u64*)&Wos[i*HID + base];
#pragma unroll
        for (int j = 0; j < 5; j++) acc[j] = fma2(c2, wr[j], acc[j]);
    }
    float aoc[10];
#pragma unroll
    for (int j = 0; j < 5; j++) {
        float2 v = upk2(acc[j]);
        float2 xv = *(const float2*)&x[(size_t)t*HID + base + 2*j];
        aoc[2*j]   = v.x + xv.x;
        aoc[2*j+1] = v.y + xv.y;
        *(float2*)&ao_s[tok*HID + base + 2*j] = make_float2(aoc[2*j], aoc[2*j+1]);
    }
    __syncthreads();

    // LN2, single pass
    float s1 = 0.f, s2 = 0.f;
    {
        const float4* ar = (const float4*)&ao_s[tok*HID];
#pragma unroll
        for (int i4 = 0; i4 < 10; i4++) {
            float4 v = ar[i4];
            s1 += v.x + v.y + v.z + v.w;
            s2 += v.x*v.x + v.y*v.y + v.z*v.z + v.w*v.w;
        }
    }
    float mu = s1 * (1.f/HID);
    float var = s2 * (1.f/HID) - mu*mu;
    float rs = rsqrtf(var + 1e-5f);
#pragma unroll
    for (int i = base; i < base + 10; i++) {
        float hv = (ao_s[tok*HID + i] - mu)*rs*g2s[i] + b2gs[i];
        h2s[tok*41 + i] = pk2(hv, hv);
    }
    __syncthreads();

    // inter[ibase..ibase+5) = gelu(h2 @ W1 + b1)
    const int ibase = part * 5;
    {
        float it[5];
#pragma unroll
        for (int o = 0; o < 5; o++) it[o] = b1s[ibase + o];
#pragma unroll
        for (int i = 0; i < HID; i++) {
            float hi = *(const float*)&h2s[tok*41 + i];
            const float* wr = &W1s[i*INTER + ibase];
#pragma unroll
            for (int o = 0; o < 5; o++) it[o] = fmaf(hi, wr[o], it[o]);
        }
#pragma unroll
        for (int o = 0; o < 5; o++) {
            float z = it[o];
            it_s[tok*INTER + ibase + o] = 0.5f * z * (1.f + erff(z * 0.70710678118654752f));
        }
    }
    __syncthreads();

    // out[base..base+10) = inter @ W2 + b2 + ao
    u64 acc2[5];
#pragma unroll
    for (int j = 0; j < 5; j++) acc2[j] = *(const u64*)&b2s[base + 2*j];
#pragma unroll
    for (int i = 0; i < INTER; i++) {
        float iv = it_s[tok*INTER + i];
        u64 i2 = pk2(iv, iv);
        const u64* wr = (const u64*)&W2s[i*HID + base];
#pragma unroll
        for (int j = 0; j < 5; j++) acc2[j] = fma2(i2, wr[j], acc2[j]);
    }
#pragma unroll
    for (int j = 0; j < 5; j++) {
        float2 v = upk2(acc2[j]);
        float2 o; o.x = v.x + aoc[2*j]; o.y = v.y + aoc[2*j+1];
        *(float2*)&out[(size_t)t*HID + base + 2*j] = o;
    }
}

extern "C" void kernel_launch(void* const* d_in, const int* in_sizes, int n_in,
                              void* d_out, int out_size)
{
    const float* x    = (const float*)d_in[0];
    const float* ln1g = (const float*)d_in[1];
    const float* ln1b = (const float*)d_in[2];
    const float* Wq   = (const float*)d_in[3];
    const float* bq   = (const float*)d_in[4];
    const float* Wk   = (const float*)d_in[5];
    const float* bk   = (const float*)d_in[6];
    const float* Wv   = (const float*)d_in[7];
    const float* bv   = (const float*)d_in[8];
    const float* Wo   = (const float*)d_in[9];
    const float* bo   = (const float*)d_in[10];
    const float* ln2g = (const float*)d_in[11];
    const float* ln2b = (const float*)d_in[12];
    const float* W1   = (const float*)d_in[13];
    const float* b1   = (const float*)d_in[14];
    const float* W2   = (const float*)d_in[15];
    const float* b2   = (const float*)d_in[16];
    float* out = (float*)d_out;

    k_ln_qkv<<<TT/64, 240>>>(x, ln1g, ln1b, Wq, bq, Wk, bk, Wv, bv);
    k_attn<<<NBH*2, 128>>>();
    k_out_ffn<<<TT/32, 128>>>(x, Wo, bo, ln2g, ln2b, W1, b1, W2, b2, out);
}